// round 16
// baseline (speedup 1.0000x reference)
#include <cuda_runtime.h>
#include <cuda_fp16.h>
#include <math.h>
#include <stdint.h>

#define NN 50000
#define EE 600000
#define DD 128
#define HH 8
#define INV_SCALE 0.25f   // 1/sqrt(16)
#define NPAD 50176        // 196 * 256
#define NB 196

// ---------------- scratch (static device allocations; no cudaMalloc) ----------
// NOTE: zero-initialized at module load; zero_tail re-zeroes counters each run.
__device__ __half g_Qh[(size_t)NN * DD];
__device__ __half g_Kh[(size_t)NN * DD];
__device__ __half g_Vh[(size_t)NN * DD];
__device__ __half g_acch[(size_t)NN * DD];
__device__ int    g_cnt[NPAD];
__device__ int    g_cur[NPAD];
__device__ int    g_off[NPAD];
__device__ int    g_bsum[256];
__device__ int    g_arrive;
__device__ uint2  g_sedge[EE];    // {col, bits(edge_attr)} sorted by row

// ---------------- helpers -------------------------------------------------------
__device__ __forceinline__ uint32_t smem_u32(const void* p) {
    uint32_t a;
    asm("{ .reg .u64 t; cvta.to.shared.u64 t, %1; cvt.u32.u64 %0, t; }" : "=r"(a) : "l"(p));
    return a;
}
__device__ __forceinline__ uint32_t pack_f16(float x, float y) {
    __half2 t = __floats2half2_rn(x, y);
    return *(uint32_t*)&t;
}
__device__ __forceinline__ void ldmatrix_x4(uint32_t& r0, uint32_t& r1,
                                            uint32_t& r2, uint32_t& r3, uint32_t addr) {
    asm volatile("ldmatrix.sync.aligned.m8n8.x4.shared.b16 {%0,%1,%2,%3}, [%4];"
                 : "=r"(r0), "=r"(r1), "=r"(r2), "=r"(r3) : "r"(addr));
}
__device__ __forceinline__ void mma_f16(float* c, const uint32_t* a, const uint32_t* b) {
    asm volatile(
        "mma.sync.aligned.m16n8k16.row.col.f32.f16.f16.f32 "
        "{%0,%1,%2,%3}, {%4,%5,%6,%7}, {%8,%9}, {%0,%1,%2,%3};"
        : "+f"(c[0]), "+f"(c[1]), "+f"(c[2]), "+f"(c[3])
        : "r"(a[0]), "r"(a[1]), "r"(a[2]), "r"(a[3]), "r"(b[0]), "r"(b[1]));
}

// block-local edge_index dtype detection (int64 LE values in [0,5e4): odd words 0)
__device__ __forceinline__ int block_is64(const unsigned int* __restrict__ ei32,
                                          int* s_flag) {
    if (threadIdx.x == 0) {
        unsigned int acc = 0;
#pragma unroll
        for (int j = 0; j < 64; j++) acc |= ei32[2 * j + 1];
        *s_flag = (acc == 0) ? 1 : 0;
    }
    __syncthreads();
    return *s_flag;
}

// ---------------- counting sort: hist -> fused scan -> permute -------------------
__global__ __launch_bounds__(256) void hist_kernel(const unsigned int* __restrict__ ei32) {
    __shared__ int s_is64;
    int is64 = block_is64(ei32, &s_is64);
    int i = blockIdx.x * blockDim.x + threadIdx.x;
    if (i >= EE) return;
    int row = is64 ? (int)ei32[2 * (size_t)i] : (int)ei32[i];
    atomicAdd(&g_cnt[row], 1);
}

// scan1 + fused scan2 (last-arriving block scans the 196 block sums)
__global__ __launch_bounds__(256) void scan_kernel() {
    __shared__ int s[256];
    __shared__ int s_last;
    int tid = threadIdx.x;
    int i = blockIdx.x * 256 + tid;
    int v = g_cnt[i];
    s[tid] = v;
    __syncthreads();
#pragma unroll
    for (int d = 1; d < 256; d <<= 1) {
        int t = (tid >= d) ? s[tid - d] : 0;
        __syncthreads();
        s[tid] += t;
        __syncthreads();
    }
    g_off[i] = s[tid] - v;
    if (tid == 255) g_bsum[blockIdx.x] = s[255];

    __threadfence();
    if (tid == 0) {
        int t = atomicAdd(&g_arrive, 1);
        s_last = (t == NB - 1) ? 1 : 0;
    }
    __syncthreads();
    if (s_last) {
        int v2 = (tid < NB) ? g_bsum[tid] : 0;
        s[tid] = v2;
        __syncthreads();
#pragma unroll
        for (int d = 1; d < 256; d <<= 1) {
            int t = (tid >= d) ? s[tid - d] : 0;
            __syncthreads();
            s[tid] += t;
            __syncthreads();
        }
        g_bsum[tid] = s[tid] - v2;
    }
}

__global__ __launch_bounds__(256) void permute_kernel(
    const unsigned int* __restrict__ ei32, const float* __restrict__ ea)
{
    __shared__ int s_is64;
    int is64 = block_is64(ei32, &s_is64);
    int i = blockIdx.x * blockDim.x + threadIdx.x;
    if (i >= EE) return;
    int row, col;
    if (is64) {
        row = (int)ei32[2 * (size_t)i];
        col = (int)ei32[2 * ((size_t)EE + i)];
    } else {
        row = (int)ei32[i];
        col = (int)ei32[(size_t)EE + i];
    }
    int pos = g_off[row] + g_bsum[row >> 8] + atomicAdd(&g_cur[row], 1);
    g_sedge[pos] = make_uint2((unsigned)col, __float_as_uint(ea[i]));
}

// ---------------- tail: re-zero counters for next replay -------------------------
__global__ __launch_bounds__(256) void zero_tail_kernel() {
    int i = blockIdx.x * blockDim.x + threadIdx.x;
    if (i < NPAD) { g_cnt[i] = 0; g_cur[i] = 0; }
    if (i == 0) g_arrive = 0;
}

// ---------------- tensor-core GEMM (single-pass fp16, fp32 accumulate) ----------
// B is staged in-kernel from fp32 W (row-major [k][n]) with transpose+convert.
// A_HALF: A is fp16 (direct copy); else fp32 (convert). OUT_HALF: fp16 store.
#define PS      (128 * 136)
#define SMEM_GEMM (2 * PS * 2)       // 69632 bytes: sA + sB

template <bool A_HALF, bool OUT_HALF>
__device__ __forceinline__ void gemm_mma_body(
    const void* __restrict__ Av, const float* __restrict__ W,
    const float* __restrict__ bias, void* __restrict__ Cv, int M)
{
    extern __shared__ __half smem[];
    const uint32_t sb = smem_u32(smem);
    const int tid = threadIdx.x;
    const int lane = tid & 31;
    const int wid = tid >> 5;
    const int warp_m = wid >> 1;
    const int warp_n = wid & 1;
    const int block_row = blockIdx.x * 128;

    // ---- stage B: read fp32 W[k][n], write fp16 sB[n*136+k] (transpose) ----
    {
        __half* sB = smem + PS;
#pragma unroll
        for (int j = 0; j < 16; j++) {
            int f4 = tid + 256 * j;          // float4 index, 0..4095
            float4 w = *(const float4*)(W + (size_t)f4 * 4);
            int k = (f4 * 4) >> 7;
            int n = (f4 * 4) & 127;
            sB[(n + 0) * 136 + k] = __float2half_rn(w.x);
            sB[(n + 1) * 136 + k] = __float2half_rn(w.y);
            sB[(n + 2) * 136 + k] = __float2half_rn(w.z);
            sB[(n + 3) * 136 + k] = __float2half_rn(w.w);
        }
    }

    // ---- stage A tile into smem (stride 136), converting if fp32 ----
    {
        int r = tid >> 1;
        int half = tid & 1;
        int gr = block_row + r;
        uint32_t* dst = (uint32_t*)smem + (r * 136 + half * 64) / 2;
        if (gr < M) {
            if (A_HALF) {
                const uint4* Arow = (const uint4*)((const __half*)Av + (size_t)gr * 128 + half * 64);
#pragma unroll
                for (int i = 0; i < 8; i++) {
                    uint4 w = Arow[i];
                    dst[4 * i]     = w.x;
                    dst[4 * i + 1] = w.y;
                    dst[4 * i + 2] = w.z;
                    dst[4 * i + 3] = w.w;
                }
            } else {
                const float4* Arow = (const float4*)((const float*)Av + (size_t)gr * 128 + half * 64);
#pragma unroll
                for (int i = 0; i < 16; i++) {
                    float4 a = Arow[i];
                    dst[2 * i]     = pack_f16(a.x, a.y);
                    dst[2 * i + 1] = pack_f16(a.z, a.w);
                }
            }
        } else {
#pragma unroll
            for (int i = 0; i < 32; i++) dst[i] = 0u;
        }
    }
    __syncthreads();

    uint32_t aAddr[2];
#pragma unroll
    for (int mt = 0; mt < 2; mt++)
        aAddr[mt] = sb + ((warp_m * 32 + mt * 16 + (lane & 15)) * 136 +
                          ((lane >> 4) << 3)) * 2;
    uint32_t bAddr[4];
#pragma unroll
    for (int g = 0; g < 4; g++)
        bAddr[g] = sb + PS * 2 +
                   ((warp_n * 64 + g * 16 + ((lane >> 4) << 3) + (lane & 7)) * 136 +
                    (((lane >> 3) & 1) << 3)) * 2;

    float c[2][8][4];
#pragma unroll
    for (int mt = 0; mt < 2; mt++)
#pragma unroll
        for (int nt = 0; nt < 8; nt++)
#pragma unroll
            for (int j = 0; j < 4; j++) c[mt][nt][j] = 0.0f;

#pragma unroll
    for (int k = 0; k < 8; k++) {
        const uint32_t kb = (uint32_t)k * 32;
        uint32_t a[2][4];
#pragma unroll
        for (int mt = 0; mt < 2; mt++)
            ldmatrix_x4(a[mt][0], a[mt][1], a[mt][2], a[mt][3], aAddr[mt] + kb);
        uint32_t b[8][2];
#pragma unroll
        for (int g = 0; g < 4; g++) {
            uint32_t r0, r1, r2, r3;
            ldmatrix_x4(r0, r1, r2, r3, bAddr[g] + kb);
            b[2 * g][0] = r0; b[2 * g][1] = r1;
            b[2 * g + 1][0] = r2; b[2 * g + 1][1] = r3;
        }
#pragma unroll
        for (int mt = 0; mt < 2; mt++)
#pragma unroll
            for (int nt = 0; nt < 8; nt++)
                mma_f16(c[mt][nt], a[mt], b[nt]);
    }

#pragma unroll
    for (int mt = 0; mt < 2; mt++) {
        int m0 = block_row + warp_m * 32 + mt * 16 + (lane >> 2);
#pragma unroll
        for (int nt = 0; nt < 8; nt++) {
            int n0 = warp_n * 64 + nt * 8 + (lane & 3) * 2;
            float bx = __ldg(bias + n0), by = __ldg(bias + n0 + 1);
            if (OUT_HALF) {
                __half* C = (__half*)Cv;
                if (m0 < M)
                    *(__half2*)(C + (size_t)m0 * 128 + n0) =
                        __floats2half2_rn(c[mt][nt][0] + bx, c[mt][nt][1] + by);
                if (m0 + 8 < M)
                    *(__half2*)(C + (size_t)(m0 + 8) * 128 + n0) =
                        __floats2half2_rn(c[mt][nt][2] + bx, c[mt][nt][3] + by);
            } else {
                float* C = (float*)Cv;
                if (m0 < M)
                    *(float2*)(C + (size_t)m0 * 128 + n0) =
                        make_float2(c[mt][nt][0] + bx, c[mt][nt][1] + by);
                if (m0 + 8 < M)
                    *(float2*)(C + (size_t)(m0 + 8) * 128 + n0) =
                        make_float2(c[mt][nt][2] + bx, c[mt][nt][3] + by);
            }
        }
    }
}

__global__ __launch_bounds__(256) void gemm_qkv_mma(
    const float* __restrict__ x,
    const float* __restrict__ Wq, const float* __restrict__ bq,
    const float* __restrict__ Wk, const float* __restrict__ bk,
    const float* __restrict__ Wv, const float* __restrict__ bv, int M)
{
    int m = blockIdx.y;
    const float* W    = (m == 0) ? Wq : (m == 1) ? Wk : Wv;
    const float* bias = (m == 0) ? bq : (m == 1) ? bk : bv;
    __half* C = (m == 0) ? g_Qh : (m == 1) ? g_Kh : g_Vh;
    gemm_mma_body<false, true>(x, W, bias, C, M);
}

__global__ __launch_bounds__(256) void gemm_out_mma(
    const float* __restrict__ Wo, const float* __restrict__ bo,
    float* __restrict__ out, int M)
{
    gemm_mma_body<true, false>(g_acch, Wo, bo, out, M);
}

// ---------------- node-centric aggregation (gather-side; fp16 store) -------------
__global__ __launch_bounds__(256) void aggregate_kernel()
{
    int n = (blockIdx.x * blockDim.x + threadIdx.x) >> 5;
    if (n >= NN) return;
    int lane = threadIdx.x & 31;

    int base = g_off[n] + g_bsum[n >> 8];
    int deg  = g_cnt[n];

    uint2 qw = __ldg(((const uint2*)(g_Qh + (size_t)n * 128)) + lane);
    float2 qa = __half22float2(*(__half2*)&qw.x);
    float2 qb = __half22float2(*(__half2*)&qw.y);

    float a0 = 0.f, a1 = 0.f, a2 = 0.f, a3 = 0.f;
    float ssum = 0.f;

    if (deg > 0) {
        uint2 rec = __ldg(&g_sedge[base]);
        for (int i = 0; i < deg; i++) {
            int col = (int)rec.x;
            float eav = __uint_as_float(rec.y);
            if (i + 1 < deg) rec = __ldg(&g_sedge[base + i + 1]);

            uint2 kw = __ldg(((const uint2*)(g_Kh + (size_t)col * 128)) + lane);
            uint2 vw = __ldg(((const uint2*)(g_Vh + (size_t)col * 128)) + lane);

            float2 ka = __half22float2(*(__half2*)&kw.x);
            float2 kb = __half22float2(*(__half2*)&kw.y);
            float p = qa.x * ka.x + qa.y * ka.y + qb.x * kb.x + qb.y * kb.y;
            p += __shfl_xor_sync(0xFFFFFFFFu, p, 1);
            p += __shfl_xor_sync(0xFFFFFFFFu, p, 2);

            float s = __expf(fmaf(p, INV_SCALE, eav));
            ssum += s;

            float2 va = __half22float2(*(__half2*)&vw.x);
            float2 vb = __half22float2(*(__half2*)&vw.y);
            a0 = fmaf(s, va.x, a0);
            a1 = fmaf(s, va.y, a1);
            a2 = fmaf(s, vb.x, a2);
            a3 = fmaf(s, vb.y, a3);
        }
    }

    float inv = 1.0f / (ssum + 1e-8f);
    __half2 h0 = __floats2half2_rn(a0 * inv, a1 * inv);
    __half2 h1 = __floats2half2_rn(a2 * inv, a3 * inv);
    uint2 o = make_uint2(*(uint32_t*)&h0, *(uint32_t*)&h1);
    *(uint2*)(g_acch + (size_t)n * 128 + lane * 4) = o;
}

// ---------------- launch ----------------------------------------------------------
extern "C" void kernel_launch(void* const* d_in, const int* in_sizes, int n_in,
                              void* d_out, int out_size)
{
    const float*        x   = (const float*)d_in[0];
    const unsigned int* ei  = (const unsigned int*)d_in[1];
    const float*        ea  = (const float*)d_in[2];
    const float*        Wq  = (const float*)d_in[3];
    const float*        bq  = (const float*)d_in[4];
    const float*        Wk  = (const float*)d_in[5];
    const float*        bk  = (const float*)d_in[6];
    const float*        Wv  = (const float*)d_in[7];
    const float*        bv  = (const float*)d_in[8];
    const float*        Wo  = (const float*)d_in[9];
    const float*        bo  = (const float*)d_in[10];
    float*              out = (float*)d_out;

    static cudaStream_t sB = nullptr;
    static cudaEvent_t  evFork = nullptr, evJoin = nullptr, evAgg = nullptr, evZ = nullptr;
    if (sB == nullptr) {
        cudaStreamCreateWithFlags(&sB, cudaStreamNonBlocking);
        cudaEventCreateWithFlags(&evFork, cudaEventDisableTiming);
        cudaEventCreateWithFlags(&evJoin, cudaEventDisableTiming);
        cudaEventCreateWithFlags(&evAgg, cudaEventDisableTiming);
        cudaEventCreateWithFlags(&evZ, cudaEventDisableTiming);
        cudaFuncSetAttribute(gemm_qkv_mma, cudaFuncAttributeMaxDynamicSharedMemorySize, SMEM_GEMM);
        cudaFuncSetAttribute(gemm_out_mma, cudaFuncAttributeMaxDynamicSharedMemorySize, SMEM_GEMM);
    }

    // ---- fork: side stream = QKV GEMM (in-kernel W transpose; no prep) ----
    cudaEventRecord(evFork, 0);
    cudaStreamWaitEvent(sB, evFork, 0);
    {
        dim3 gridq((NN + 127) / 128, 3);
        gemm_qkv_mma<<<gridq, 256, SMEM_GEMM, sB>>>(x, Wq, bq, Wk, bk, Wv, bv, NN);
    }
    cudaEventRecord(evJoin, sB);

    // ---- capture stream = edge counting sort (counters pre-zeroed by tail) ----
    hist_kernel<<<(EE + 255) / 256, 256>>>(ei);
    scan_kernel<<<NB, 256>>>();
    permute_kernel<<<(EE + 255) / 256, 256>>>(ei, ea);

    // ---- join, aggregate, output projection ----
    cudaStreamWaitEvent(0, evJoin, 0);
    aggregate_kernel<<<(NN * 32 + 255) / 256, 256>>>();
    cudaEventRecord(evAgg, 0);
    gemm_out_mma<<<(NN + 127) / 128, 256, SMEM_GEMM>>>(Wo, bo, out, NN);

    // ---- tail: re-zero counters for next replay (parallel with out GEMM) ----
    cudaStreamWaitEvent(sB, evAgg, 0);
    zero_tail_kernel<<<NPAD / 256, 256, 0, sB>>>();
    cudaEventRecord(evZ, sB);
    cudaStreamWaitEvent(0, evZ, 0);
}

// round 17
// speedup vs baseline: 1.3106x; 1.3106x over previous
#include <cuda_runtime.h>
#include <cuda_fp16.h>
#include <math.h>
#include <stdint.h>

#define NN 50000
#define EE 600000
#define DD 128
#define HH 8
#define INV_SCALE 0.25f   // 1/sqrt(16)
#define NPAD 50176        // 196 * 256
#define NB 196

// ---------------- scratch (static device allocations; no cudaMalloc) ----------
// Zero-initialized at module load; zero_tail re-zeroes counters after each run.
__device__ __half g_Qh[(size_t)NN * DD];
__device__ __half g_Kh[(size_t)NN * DD];
__device__ __half g_Vh[(size_t)NN * DD];
__device__ __half g_acch[(size_t)NN * DD];
__device__ int    g_cnt[NPAD];
__device__ int    g_cur[NPAD];
__device__ int    g_off[NPAD];
__device__ int    g_bsum[256];
__device__ int    g_arrive;
__device__ uint2  g_sedge[EE];    // {col, bits(edge_attr)} sorted by row
// pre-transposed weights fp16, stored N x K row-major: g_B[mat][n*128+k] = W[k][n]
__device__ __align__(16) __half g_B[4][128 * 128];

// ---------------- helpers -------------------------------------------------------
__device__ __forceinline__ uint32_t smem_u32(const void* p) {
    uint32_t a;
    asm("{ .reg .u64 t; cvta.to.shared.u64 t, %1; cvt.u32.u64 %0, t; }" : "=r"(a) : "l"(p));
    return a;
}
__device__ __forceinline__ uint32_t pack_f16(float x, float y) {
    __half2 t = __floats2half2_rn(x, y);
    return *(uint32_t*)&t;
}
__device__ __forceinline__ void ldmatrix_x4(uint32_t& r0, uint32_t& r1,
                                            uint32_t& r2, uint32_t& r3, uint32_t addr) {
    asm volatile("ldmatrix.sync.aligned.m8n8.x4.shared.b16 {%0,%1,%2,%3}, [%4];"
                 : "=r"(r0), "=r"(r1), "=r"(r2), "=r"(r3) : "r"(addr));
}
__device__ __forceinline__ void mma_f16(float* c, const uint32_t* a, const uint32_t* b) {
    asm volatile(
        "mma.sync.aligned.m16n8k16.row.col.f32.f16.f16.f32 "
        "{%0,%1,%2,%3}, {%4,%5,%6,%7}, {%8,%9}, {%0,%1,%2,%3};"
        : "+f"(c[0]), "+f"(c[1]), "+f"(c[2]), "+f"(c[3])
        : "r"(a[0]), "r"(a[1]), "r"(a[2]), "r"(a[3]), "r"(b[0]), "r"(b[1]));
}

// block-local edge_index dtype detection (int64 LE values in [0,5e4): odd words 0)
__device__ __forceinline__ int block_is64(const unsigned int* __restrict__ ei32,
                                          int* s_flag) {
    if (threadIdx.x == 0) {
        unsigned int acc = 0;
#pragma unroll
        for (int j = 0; j < 64; j++) acc |= ei32[2 * j + 1];
        *s_flag = (acc == 0) ? 1 : 0;
    }
    __syncthreads();
    return *s_flag;
}

// ---------------- counting sort: hist -> fused scan -> permute -------------------
__global__ __launch_bounds__(256) void hist_kernel(const unsigned int* __restrict__ ei32) {
    __shared__ int s_is64;
    int is64 = block_is64(ei32, &s_is64);
    int i = blockIdx.x * blockDim.x + threadIdx.x;
    if (i >= EE) return;
    int row = is64 ? (int)ei32[2 * (size_t)i] : (int)ei32[i];
    atomicAdd(&g_cnt[row], 1);
}

// scan1 + fused scan2 (last-arriving block scans the 196 block sums)
__global__ __launch_bounds__(256) void scan_kernel() {
    __shared__ int s[256];
    __shared__ int s_last;
    int tid = threadIdx.x;
    int i = blockIdx.x * 256 + tid;
    int v = g_cnt[i];
    s[tid] = v;
    __syncthreads();
#pragma unroll
    for (int d = 1; d < 256; d <<= 1) {
        int t = (tid >= d) ? s[tid - d] : 0;
        __syncthreads();
        s[tid] += t;
        __syncthreads();
    }
    g_off[i] = s[tid] - v;
    if (tid == 255) g_bsum[blockIdx.x] = s[255];

    __threadfence();
    if (tid == 0) {
        int t = atomicAdd(&g_arrive, 1);
        s_last = (t == NB - 1) ? 1 : 0;
    }
    __syncthreads();
    if (s_last) {
        int v2 = (tid < NB) ? g_bsum[tid] : 0;
        s[tid] = v2;
        __syncthreads();
#pragma unroll
        for (int d = 1; d < 256; d <<= 1) {
            int t = (tid >= d) ? s[tid - d] : 0;
            __syncthreads();
            s[tid] += t;
            __syncthreads();
        }
        g_bsum[tid] = s[tid] - v2;
    }
}

__global__ __launch_bounds__(256) void permute_kernel(
    const unsigned int* __restrict__ ei32, const float* __restrict__ ea)
{
    __shared__ int s_is64;
    int is64 = block_is64(ei32, &s_is64);
    int i = blockIdx.x * blockDim.x + threadIdx.x;
    if (i >= EE) return;
    int row, col;
    if (is64) {
        row = (int)ei32[2 * (size_t)i];
        col = (int)ei32[2 * ((size_t)EE + i)];
    } else {
        row = (int)ei32[i];
        col = (int)ei32[(size_t)EE + i];
    }
    int pos = g_off[row] + g_bsum[row >> 8] + atomicAdd(&g_cur[row], 1);
    g_sedge[pos] = make_uint2((unsigned)col, __float_as_uint(ea[i]));
}

// ---------------- tail: re-zero counters for next replay -------------------------
__global__ __launch_bounds__(256) void zero_tail_kernel() {
    int i = blockIdx.x * blockDim.x + threadIdx.x;
    if (i < NPAD) { g_cnt[i] = 0; g_cur[i] = 0; }
    if (i == 0) g_arrive = 0;
}

// ---------------- weight prep: transpose -> fp16 (dedicated, conflict-free) ------
__global__ __launch_bounds__(256) void prep_kernel(
    const float* __restrict__ Wq, const float* __restrict__ Wk,
    const float* __restrict__ Wv, const float* __restrict__ Wo)
{
    int m = blockIdx.y;
    const float* src = (m == 0) ? Wq : (m == 1) ? Wk : (m == 2) ? Wv : Wo;
    int idx = blockIdx.x * 256 + threadIdx.x;
    int n = idx >> 7, k = idx & 127;
    g_B[m][n * 128 + k] = __float2half_rn(src[k * 128 + n]);
}

// ---------------- tensor-core GEMM (single-pass fp16, fp32 accumulate) ----------
#define PS      (128 * 136)
#define SMEM_GEMM (2 * PS * 2)       // 69632 bytes: sA + sB

template <bool A_HALF, bool OUT_HALF>
__device__ __forceinline__ void gemm_mma_body(
    const void* __restrict__ Av, const __half* __restrict__ Bsrc,
    const float* __restrict__ bias, void* __restrict__ Cv, int M)
{
    extern __shared__ __half smem[];
    const uint32_t sb = smem_u32(smem);
    const int tid = threadIdx.x;
    const int lane = tid & 31;
    const int wid = tid >> 5;
    const int warp_m = wid >> 1;
    const int warp_n = wid & 1;
    const int block_row = blockIdx.x * 128;

    // ---- load B plane (pre-transposed fp16) into sB with stride 136 ----
    {
        const uint32_t* src = (const uint32_t*)Bsrc;
        uint32_t* dst = (uint32_t*)(smem + PS);
#pragma unroll 8
        for (int i = tid; i < 8192; i += 256) {
            int row = i >> 6, colw = i & 63;
            dst[row * 68 + colw] = src[i];
        }
    }

    // ---- stage A tile into smem (stride 136), converting if fp32 ----
    {
        int r = tid >> 1;
        int half = tid & 1;
        int gr = block_row + r;
        uint32_t* dst = (uint32_t*)smem + (r * 136 + half * 64) / 2;
        if (gr < M) {
            if (A_HALF) {
                const uint4* Arow = (const uint4*)((const __half*)Av + (size_t)gr * 128 + half * 64);
#pragma unroll
                for (int i = 0; i < 8; i++) {
                    uint4 w = Arow[i];
                    dst[4 * i]     = w.x;
                    dst[4 * i + 1] = w.y;
                    dst[4 * i + 2] = w.z;
                    dst[4 * i + 3] = w.w;
                }
            } else {
                const float4* Arow = (const float4*)((const float*)Av + (size_t)gr * 128 + half * 64);
#pragma unroll
                for (int i = 0; i < 16; i++) {
                    float4 a = Arow[i];
                    dst[2 * i]     = pack_f16(a.x, a.y);
                    dst[2 * i + 1] = pack_f16(a.z, a.w);
                }
            }
        } else {
#pragma unroll
            for (int i = 0; i < 32; i++) dst[i] = 0u;
        }
    }
    __syncthreads();

    uint32_t aAddr[2];
#pragma unroll
    for (int mt = 0; mt < 2; mt++)
        aAddr[mt] = sb + ((warp_m * 32 + mt * 16 + (lane & 15)) * 136 +
                          ((lane >> 4) << 3)) * 2;
    uint32_t bAddr[4];
#pragma unroll
    for (int g = 0; g < 4; g++)
        bAddr[g] = sb + PS * 2 +
                   ((warp_n * 64 + g * 16 + ((lane >> 4) << 3) + (lane & 7)) * 136 +
                    (((lane >> 3) & 1) << 3)) * 2;

    float c[2][8][4];
#pragma unroll
    for (int mt = 0; mt < 2; mt++)
#pragma unroll
        for (int nt = 0; nt < 8; nt++)
#pragma unroll
            for (int j = 0; j < 4; j++) c[mt][nt][j] = 0.0f;

#pragma unroll
    for (int k = 0; k < 8; k++) {
        const uint32_t kb = (uint32_t)k * 32;
        uint32_t a[2][4];
#pragma unroll
        for (int mt = 0; mt < 2; mt++)
            ldmatrix_x4(a[mt][0], a[mt][1], a[mt][2], a[mt][3], aAddr[mt] + kb);
        uint32_t b[8][2];
#pragma unroll
        for (int g = 0; g < 4; g++) {
            uint32_t r0, r1, r2, r3;
            ldmatrix_x4(r0, r1, r2, r3, bAddr[g] + kb);
            b[2 * g][0] = r0; b[2 * g][1] = r1;
            b[2 * g + 1][0] = r2; b[2 * g + 1][1] = r3;
        }
#pragma unroll
        for (int mt = 0; mt < 2; mt++)
#pragma unroll
            for (int nt = 0; nt < 8; nt++)
                mma_f16(c[mt][nt], a[mt], b[nt]);
    }

#pragma unroll
    for (int mt = 0; mt < 2; mt++) {
        int m0 = block_row + warp_m * 32 + mt * 16 + (lane >> 2);
#pragma unroll
        for (int nt = 0; nt < 8; nt++) {
            int n0 = warp_n * 64 + nt * 8 + (lane & 3) * 2;
            float bx = __ldg(bias + n0), by = __ldg(bias + n0 + 1);
            if (OUT_HALF) {
                __half* C = (__half*)Cv;
                if (m0 < M)
                    *(__half2*)(C + (size_t)m0 * 128 + n0) =
                        __floats2half2_rn(c[mt][nt][0] + bx, c[mt][nt][1] + by);
                if (m0 + 8 < M)
                    *(__half2*)(C + (size_t)(m0 + 8) * 128 + n0) =
                        __floats2half2_rn(c[mt][nt][2] + bx, c[mt][nt][3] + by);
            } else {
                float* C = (float*)Cv;
                if (m0 < M)
                    *(float2*)(C + (size_t)m0 * 128 + n0) =
                        make_float2(c[mt][nt][0] + bx, c[mt][nt][1] + by);
                if (m0 + 8 < M)
                    *(float2*)(C + (size_t)(m0 + 8) * 128 + n0) =
                        make_float2(c[mt][nt][2] + bx, c[mt][nt][3] + by);
            }
        }
    }
}

__global__ __launch_bounds__(256) void gemm_qkv_mma(
    const float* __restrict__ x,
    const float* __restrict__ bq, const float* __restrict__ bk,
    const float* __restrict__ bv, int M)
{
    int m = blockIdx.y;
    const float* bias = (m == 0) ? bq : (m == 1) ? bk : bv;
    __half* C = (m == 0) ? g_Qh : (m == 1) ? g_Kh : g_Vh;
    gemm_mma_body<false, true>(x, &g_B[m][0], bias, C, M);
}

__global__ __launch_bounds__(256) void gemm_out_mma(
    const float* __restrict__ bo, float* __restrict__ out, int M)
{
    gemm_mma_body<true, false>(g_acch, &g_B[3][0], bo, out, M);
}

// ---------------- node-centric aggregation (gather-side; fp16 store) -------------
__global__ __launch_bounds__(256) void aggregate_kernel()
{
    int n = (blockIdx.x * blockDim.x + threadIdx.x) >> 5;
    if (n >= NN) return;
    int lane = threadIdx.x & 31;

    int base = g_off[n] + g_bsum[n >> 8];
    int deg  = g_cnt[n];

    uint2 qw = __ldg(((const uint2*)(g_Qh + (size_t)n * 128)) + lane);
    float2 qa = __half22float2(*(__half2*)&qw.x);
    float2 qb = __half22float2(*(__half2*)&qw.y);

    float a0 = 0.f, a1 = 0.f, a2 = 0.f, a3 = 0.f;
    float ssum = 0.f;

    if (deg > 0) {
        uint2 rec = __ldg(&g_sedge[base]);
        for (int i = 0; i < deg; i++) {
            int col = (int)rec.x;
            float eav = __uint_as_float(rec.y);
            if (i + 1 < deg) rec = __ldg(&g_sedge[base + i + 1]);

            uint2 kw = __ldg(((const uint2*)(g_Kh + (size_t)col * 128)) + lane);
            uint2 vw = __ldg(((const uint2*)(g_Vh + (size_t)col * 128)) + lane);

            float2 ka = __half22float2(*(__half2*)&kw.x);
            float2 kb = __half22float2(*(__half2*)&kw.y);
            float p = qa.x * ka.x + qa.y * ka.y + qb.x * kb.x + qb.y * kb.y;
            p += __shfl_xor_sync(0xFFFFFFFFu, p, 1);
            p += __shfl_xor_sync(0xFFFFFFFFu, p, 2);

            float s = __expf(fmaf(p, INV_SCALE, eav));
            ssum += s;

            float2 va = __half22float2(*(__half2*)&vw.x);
            float2 vb = __half22float2(*(__half2*)&vw.y);
            a0 = fmaf(s, va.x, a0);
            a1 = fmaf(s, va.y, a1);
            a2 = fmaf(s, vb.x, a2);
            a3 = fmaf(s, vb.y, a3);
        }
    }

    float inv = 1.0f / (ssum + 1e-8f);
    __half2 h0 = __floats2half2_rn(a0 * inv, a1 * inv);
    __half2 h1 = __floats2half2_rn(a2 * inv, a3 * inv);
    uint2 o = make_uint2(*(uint32_t*)&h0, *(uint32_t*)&h1);
    *(uint2*)(g_acch + (size_t)n * 128 + lane * 4) = o;
}

// ---------------- launch ----------------------------------------------------------
extern "C" void kernel_launch(void* const* d_in, const int* in_sizes, int n_in,
                              void* d_out, int out_size)
{
    const float*        x   = (const float*)d_in[0];
    const unsigned int* ei  = (const unsigned int*)d_in[1];
    const float*        ea  = (const float*)d_in[2];
    const float*        Wq  = (const float*)d_in[3];
    const float*        bq  = (const float*)d_in[4];
    const float*        Wk  = (const float*)d_in[5];
    const float*        bk  = (const float*)d_in[6];
    const float*        Wv  = (const float*)d_in[7];
    const float*        bv  = (const float*)d_in[8];
    const float*        Wo  = (const float*)d_in[9];
    const float*        bo  = (const float*)d_in[10];
    float*              out = (float*)d_out;

    static cudaStream_t sB = nullptr;
    static cudaEvent_t  evFork = nullptr, evJoin = nullptr, evAgg = nullptr, evZ = nullptr;
    if (sB == nullptr) {
        cudaStreamCreateWithFlags(&sB, cudaStreamNonBlocking);
        cudaEventCreateWithFlags(&evFork, cudaEventDisableTiming);
        cudaEventCreateWithFlags(&evJoin, cudaEventDisableTiming);
        cudaEventCreateWithFlags(&evAgg, cudaEventDisableTiming);
        cudaEventCreateWithFlags(&evZ, cudaEventDisableTiming);
        cudaFuncSetAttribute(gemm_qkv_mma, cudaFuncAttributeMaxDynamicSharedMemorySize, SMEM_GEMM);
        cudaFuncSetAttribute(gemm_out_mma, cudaFuncAttributeMaxDynamicSharedMemorySize, SMEM_GEMM);
    }

    // ---- fork: side stream = weight prep + QKV GEMM ----
    cudaEventRecord(evFork, 0);
    cudaStreamWaitEvent(sB, evFork, 0);
    {
        dim3 gridp(64, 4);
        prep_kernel<<<gridp, 256, 0, sB>>>(Wq, Wk, Wv, Wo);
        dim3 gridq((NN + 127) / 128, 3);
        gemm_qkv_mma<<<gridq, 256, SMEM_GEMM, sB>>>(x, bq, bk, bv, NN);
    }
    cudaEventRecord(evJoin, sB);

    // ---- capture stream = edge counting sort (counters pre-zeroed by tail) ----
    hist_kernel<<<(EE + 255) / 256, 256>>>(ei);
    scan_kernel<<<NB, 256>>>();
    permute_kernel<<<(EE + 255) / 256, 256>>>(ei, ea);

    // ---- join, aggregate, output projection ----
    cudaStreamWaitEvent(0, evJoin, 0);
    aggregate_kernel<<<(NN * 32 + 255) / 256, 256>>>();
    cudaEventRecord(evAgg, 0);
    gemm_out_mma<<<(NN + 127) / 128, 256, SMEM_GEMM>>>(bo, out, NN);

    // ---- tail: re-zero counters for next replay (parallel with out GEMM) ----
    cudaStreamWaitEvent(sB, evAgg, 0);
    zero_tail_kernel<<<NPAD / 256, 256, 0, sB>>>();
    cudaEventRecord(evZ, sB);
    cudaStreamWaitEvent(0, evZ, 0);
}